// round 16
// baseline (speedup 1.0000x reference)
#include <cuda_runtime.h>
#include <cuda_fp16.h>
#include <math.h>
#include <stdint.h>

// Problem constants (fixed by the dataset)
constexpr int cB  = 128;
constexpr int cT  = 16;
constexpr int cF  = 256;
constexpr int cN  = 1024;
constexpr int cE  = 8192;
constexpr int cNC = 256;               // edge indices live in [0,256)
constexpr int M1   = cB * cNC;         // 32768 compact rows
constexpr int MX   = cB * cT;          // 2048 output rows
constexpr int MEXT = M1 + MX;          // 34816

// Output layout (flattened tuple, float32): mx | new_nodes | edges | weights | T+taus
constexpr long OFF_MX = 0;
constexpr long OFF_NN = (long)cB * cT * cF;
constexpr long OFF_ED = OFF_NN + (long)cB * cN * cF;
constexpr long OFF_WT = OFF_ED + (long)cB * 2 * cE;
constexpr long OFF_TT = OFF_WT + (long)cB * cE;

// stage tile sizes (halves), stride-40 layout
constexpr int FS_A = 128 * 40;                     // 5120
constexpr int FS_B = 256 * 40;                     // 10240
// k_layer1: A dbl + B dbl + 8 AH chunks (each 128x40)
constexpr int FSMEM_BYTES = (2 * FS_A + 2 * FS_B + 8 * FS_A) * 2;  // 143360 B
// k_layer2: adj fp32 [16][256] + F 16 chunks [16][40] + B dbl [256][40]
constexpr int L2_ADJ = cT * cNC * 4;               // 16384 B
constexpr int L2_F   = 16 * (cT * 40) * 2;         // 20480 B
constexpr int L2SMEM_BYTES = L2_ADJ + L2_F + 2 * FS_B * 2;  // 77824 B

// Scratch (__device__ globals — no allocation allowed)
__device__ __half g_adjh[(long)cB * cNC * cNC];   // half adjacency (atomic build)
__device__ __half g_H  [(long)MEXT * cF];         // [compact nodes | X rows], half
__device__ __half g_HT [(long)cB * cNC * cF];     // per-batch transposed H [feat][node]
__device__ __half g_h1 [(long)MEXT * cF];         // layer-1 hidden
__device__ __half g_WT [4][cF * cF];              // Ws1^T, Wm1^T, Ws2^T, Wm2^T (half)

// ---------------------------------------------------------------------------
// helpers
// ---------------------------------------------------------------------------
__device__ __forceinline__ void cpa16(void* s, const void* g) {
    unsigned sa = (unsigned)__cvta_generic_to_shared(s);
    asm volatile("cp.async.cg.shared.global [%0], [%1], 16;" :: "r"(sa), "l"(g));
}
__device__ __forceinline__ float fast_tanh(float x) {
    float ax = fabsf(x);
    float e;
    asm("ex2.approx.f32 %0, %1;" : "=f"(e) : "f"(ax * 2.8853900817779268f));
    float t = 1.0f - __fdividef(2.0f, e + 1.0f);
    return copysignf(t, x);
}
#define LDSM4(R, ADDR)                                                          \
    asm volatile("ldmatrix.sync.aligned.m8n8.x4.shared.b16 {%0,%1,%2,%3}, [%4];"\
                 : "=r"((R)[0]), "=r"((R)[1]), "=r"((R)[2]), "=r"((R)[3])       \
                 : "r"(ADDR))
#define MMA16(ACC, AF, B0, B1)                                                  \
    asm volatile("mma.sync.aligned.m16n8k16.row.col.f32.f16.f16.f32 "           \
                 "{%0,%1,%2,%3},{%4,%5,%6,%7},{%8,%9},{%0,%1,%2,%3};"           \
                 : "+f"((ACC)[0]), "+f"((ACC)[1]), "+f"((ACC)[2]), "+f"((ACC)[3])\
                 : "r"((AF)[0]), "r"((AF)[1]), "r"((AF)[2]), "r"((AF)[3]),      \
                   "r"(B0), "r"(B1))

// compute one 32-wide k-slab (2 ldmatrix slices) from smem bases aB/bB
#define COMPUTE_SLAB(aB, bB)                                                    \
    _Pragma("unroll")                                                           \
    for (int ks = 0; ks < 2; ks++) {                                            \
        unsigned af[4][4], bf[2][4];                                            \
        _Pragma("unroll")                                                       \
        for (int mi = 0; mi < 4; mi++) LDSM4(af[mi], (aB) + aoff[mi] + ks * 32);\
        _Pragma("unroll")                                                       \
        for (int pi = 0; pi < 2; pi++) LDSM4(bf[pi], (bB) + boff[pi] + ks * 32);\
        _Pragma("unroll")                                                       \
        for (int mi = 0; mi < 4; mi++)                                          \
            _Pragma("unroll")                                                   \
            for (int ni = 0; ni < 4; ni++)                                      \
                MMA16(acc[mi][ni], af[mi],                                      \
                      bf[ni >> 1][(ni & 1) * 2], bf[ni >> 1][(ni & 1) * 2 + 1]);\
    }

// ---------------------------------------------------------------------------
// k_layer1: fused (AH = Adj@H) + (h1 = tanh(H@Ws1 + AH@Wm1)), 272 CTAs.
// (R13-proven)
// ---------------------------------------------------------------------------
__global__ __launch_bounds__(512, 1) void k_layer1(void) {
    extern __shared__ __half sm[];
    __half* As[2] = { sm,            sm + FS_A };
    __half* Bs[2] = { sm + 2 * FS_A, sm + 2 * FS_A + FS_B };
    __half* AH    = sm + 2 * FS_A + 2 * FS_B;

    const int bx = blockIdx.x;
    const bool compact = bx < 2 * cB;
    const int tid = threadIdx.x, warp = tid >> 5, lane = tid & 31;
    const int g = lane >> 2, tg = lane & 3;
    const int wm = (warp & 1) * 64;
    const int wn = (warp >> 1) * 32;
    const int arow = tid >> 2, acol = (tid & 3) * 8;

    unsigned aBase[2] = { (unsigned)__cvta_generic_to_shared(As[0]),
                          (unsigned)__cvta_generic_to_shared(As[1]) };
    unsigned bBase[2] = { (unsigned)__cvta_generic_to_shared(Bs[0]),
                          (unsigned)__cvta_generic_to_shared(Bs[1]) };
    unsigned ahBase = (unsigned)__cvta_generic_to_shared(AH);

    int aoff[4], boff[2];
#pragma unroll
    for (int mi = 0; mi < 4; mi++)
        aoff[mi] = ((wm + mi * 16 + (lane & 15)) * 40 + (lane >> 4) * 8) * 2;
    {
        int q = lane >> 3, r = lane & 7;
#pragma unroll
        for (int pi = 0; pi < 2; pi++)
            boff[pi] = ((wn + pi * 16 + (q >> 1) * 8 + r) * 40 + (q & 1) * 8) * 2;
    }

    float acc[4][4][4];
#pragma unroll
    for (int a = 0; a < 4; a++)
#pragma unroll
        for (int b = 0; b < 4; b++)
#pragma unroll
            for (int c = 0; c < 4; c++) acc[a][b][c] = 0.f;

    const __half* Hrow = g_H + (long)bx * 128 * cF;

    if (compact) {
        const __half* adjA = g_adjh + (long)bx * 128 * cNC;
        const __half* HTb  = g_HT + (long)(bx >> 1) * cNC * cF;

#define LOAD1(KBI, BUF) do {                                                    \
    int kk_ = (KBI) * 32;                                                       \
    cpa16(&As[BUF][arow * 40 + acol], adjA + (long)arow * cNC + kk_ + acol);    \
    cpa16(&Bs[BUF][arow * 40 + acol], HTb + (long)arow * cF + kk_ + acol);      \
    cpa16(&Bs[BUF][(arow + 128) * 40 + acol],                                   \
          HTb + (long)(arow + 128) * cF + kk_ + acol);                          \
    asm volatile("cp.async.commit_group;");                                     \
} while (0)

        LOAD1(0, 0);
        for (int kb = 0; kb < 8; kb++) {
            asm volatile("cp.async.wait_group 0;" ::: "memory");
            __syncthreads();
            if (kb + 1 < 8) LOAD1(kb + 1, (kb + 1) & 1);
            COMPUTE_SLAB(aBase[kb & 1], bBase[kb & 1]);
        }
#undef LOAD1

#pragma unroll
        for (int mi = 0; mi < 4; mi++) {
            int r0 = wm + mi * 16 + g;
#pragma unroll
            for (int ni = 0; ni < 4; ni++) {
                int c0 = wn + ni * 8 + tg * 2;
                __half* chp = AH + (c0 >> 5) * FS_A + (c0 & 31);
                *(__half2*)&chp[r0 * 40] =
                    __floats2half2_rn(acc[mi][ni][0], acc[mi][ni][1]);
                *(__half2*)&chp[(r0 + 8) * 40] =
                    __floats2half2_rn(acc[mi][ni][2], acc[mi][ni][3]);
                acc[mi][ni][0] = acc[mi][ni][1] = acc[mi][ni][2] = acc[mi][ni][3] = 0.f;
            }
        }
        __syncthreads();
    }

    const int nkb2 = compact ? 16 : 8;

#define LOAD2(KBI, BUF) do {                                                    \
    int kk_ = ((KBI) & 7) * 32;                                                 \
    if ((KBI) < 8)                                                              \
        cpa16(&As[BUF][arow * 40 + acol], Hrow + (long)arow * cF + kk_ + acol); \
    const __half* Wt_ = ((KBI) < 8) ? g_WT[0] : g_WT[1];                        \
    cpa16(&Bs[BUF][arow * 40 + acol], Wt_ + (long)arow * cF + kk_ + acol);      \
    cpa16(&Bs[BUF][(arow + 128) * 40 + acol],                                   \
          Wt_ + (long)(arow + 128) * cF + kk_ + acol);                          \
    asm volatile("cp.async.commit_group;");                                     \
} while (0)

    LOAD2(0, 0);
    for (int kb = 0; kb < nkb2; kb++) {
        asm volatile("cp.async.wait_group 0;" ::: "memory");
        __syncthreads();
        if (kb + 1 < nkb2) LOAD2(kb + 1, (kb + 1) & 1);
        unsigned aB = (kb < 8) ? aBase[kb & 1]
                               : (ahBase + (unsigned)(kb - 8) * (FS_A * 2));
        COMPUTE_SLAB(aB, bBase[kb & 1]);
    }
#undef LOAD2

    __half* Dh = g_h1 + (long)bx * 128 * cF;
#pragma unroll
    for (int mi = 0; mi < 4; mi++) {
        int r0 = wm + mi * 16 + g;
#pragma unroll
        for (int ni = 0; ni < 4; ni++) {
            int c0 = wn + ni * 8 + tg * 2;
            *(__half2*)&Dh[(long)r0 * cF + c0] = __floats2half2_rn(
                fast_tanh(acc[mi][ni][0]), fast_tanh(acc[mi][ni][1]));
            *(__half2*)&Dh[(long)(r0 + 8) * cF + c0] = __floats2half2_rn(
                fast_tanh(acc[mi][ni][2]), fast_tanh(acc[mi][ni][3]));
        }
    }
}

// ---------------------------------------------------------------------------
// k_layer2: fused layer-2 per batch (128 CTAs, 256 threads). (R14-proven)
// ---------------------------------------------------------------------------
__global__ __launch_bounds__(256, 1) void k_layer2(const int* __restrict__ T,
                                                   float* __restrict__ out_mx) {
    extern __shared__ char smraw[];
    float*  adj_sm = (float*)smraw;                       // [16][256]
    __half* F_sm   = (__half*)(smraw + L2_ADJ);           // 16 chunks of [16][40]
    __half* Bs[2]  = { (__half*)(smraw + L2_ADJ + L2_F),
                       (__half*)(smraw + L2_ADJ + L2_F) + FS_B };

    const int b = blockIdx.x;
    const int tid = threadIdx.x, warp = tid >> 5, lane = tid & 31;
    const int g = lane >> 2, tg = lane & 3;
    const int Tb = T[b];

    unsigned fBase = (unsigned)__cvta_generic_to_shared(F_sm);
    unsigned bsBase[2] = { (unsigned)__cvta_generic_to_shared(Bs[0]),
                           (unsigned)__cvta_generic_to_shared(Bs[1]) };

#define LOADW(KBI, BUF) do {                                                    \
    const __half* Wt_ = ((KBI) < 8) ? g_WT[2] : g_WT[3];                        \
    int kk_ = ((KBI) & 7) * 32;                                                 \
    _Pragma("unroll")                                                           \
    for (int i = 0; i < 4; i++) {                                               \
        int u = tid * 4 + i;                                                    \
        int rw = u >> 2, cw = (u & 3) * 8;                                      \
        cpa16(&Bs[BUF][rw * 40 + cw], Wt_ + (long)rw * cF + kk_ + cw);          \
    }                                                                           \
    asm volatile("cp.async.commit_group;");                                     \
} while (0)

    LOADW(0, 0);

    // ---- phase A: aggpack ----
    {
        const int c = tid;
#pragma unroll
        for (int r = 0; r < cT; r++) {
            int row = Tb + r;
            adj_sm[r * cNC + c] = (row < cNC)
                ? __half2float(g_adjh[((long)b * cNC + row) * cNC + c]) : 0.f;
        }
        __syncthreads();

        float acc2[cT];
#pragma unroll
        for (int r = 0; r < cT; r++) acc2[r] = 0.f;

        const __half* h1b = g_h1 + (long)b * cNC * cF;
#pragma unroll 4
        for (int s = 0; s < cNC; s++) {
            float v = __half2float(h1b[(long)s * cF + c]);
#pragma unroll
            for (int r = 0; r < cT; r++) acc2[r] += adj_sm[r * cNC + s] * v;
        }

        const int ch = c >> 5, cc = c & 31;
#pragma unroll
        for (int r = 0; r < cT; r++) {
            int row = Tb + r;
            __half f1 = (row < cNC) ? g_h1[((long)b * cNC + row) * cF + c]
                                    : g_h1[((long)M1 + b * cT + r) * cF + c];
            F_sm[ch * (cT * 40) + r * 40 + cc] = f1;                          // K seg 0
            F_sm[(8 + ch) * (cT * 40) + r * 40 + cc] = __float2half(acc2[r]); // K seg 1
        }
    }
    __syncthreads();

    // ---- phase B: 16x256x512 GEMM ----
    const int wn = warp * 32;
    const int aoffA = ((lane & 15) * 40 + (lane >> 4) * 8) * 2;
    int boff[2];
    {
        int q = lane >> 3, r = lane & 7;
#pragma unroll
        for (int pi = 0; pi < 2; pi++)
            boff[pi] = ((wn + pi * 16 + (q >> 1) * 8 + r) * 40 + (q & 1) * 8) * 2;
    }

    float acc[4][4];
#pragma unroll
    for (int a = 0; a < 4; a++)
#pragma unroll
        for (int c = 0; c < 4; c++) acc[a][c] = 0.f;

    for (int kb = 0; kb < 16; kb++) {
        asm volatile("cp.async.wait_group 0;" ::: "memory");
        __syncthreads();
        if (kb + 1 < 16) LOADW(kb + 1, (kb + 1) & 1);
        const unsigned bB = bsBase[kb & 1];
        const unsigned aB = fBase + (unsigned)kb * (cT * 40 * 2);

#pragma unroll
        for (int ks = 0; ks < 2; ks++) {
            unsigned af[4], bf[2][4];
            LDSM4(af, aB + aoffA + ks * 32);
#pragma unroll
            for (int pi = 0; pi < 2; pi++) LDSM4(bf[pi], bB + boff[pi] + ks * 32);
#pragma unroll
            for (int ni = 0; ni < 4; ni++)
                MMA16(acc[ni], af,
                      bf[ni >> 1][(ni & 1) * 2], bf[ni >> 1][(ni & 1) * 2 + 1]);
        }
    }
#undef LOADW

    float* Db = out_mx + (long)b * cT * cF;
#pragma unroll
    for (int ni = 0; ni < 4; ni++) {
        int c0 = wn + ni * 8 + tg * 2;
        Db[(long)g * cF + c0]           = fast_tanh(acc[ni][0]);
        Db[(long)g * cF + c0 + 1]       = fast_tanh(acc[ni][1]);
        Db[(long)(g + 8) * cF + c0]     = fast_tanh(acc[ni][2]);
        Db[(long)(g + 8) * cF + c0 + 1] = fast_tanh(acc[ni][3]);
    }
}

// ---------------------------------------------------------------------------
// staging / passthrough kernels
// ---------------------------------------------------------------------------
// compact nodes: out_nn rows + H + HT in one pass (R14-proven)
__global__ void k_nodes_compactT(const float* __restrict__ nodes, const float* __restrict__ x,
                                 const int* __restrict__ T, float* __restrict__ out_nn) {
    __shared__ __half t[32][33];
    int b = blockIdx.z;
    int x0 = blockIdx.x * 32, y0 = blockIdx.y * 32;
    int tx = threadIdx.x, ty = threadIdx.y;
    int Tb = T[b];
#pragma unroll
    for (int i = 0; i < 4; i++) {
        int n = y0 + ty + i * 8;
        int d = n - Tb;
        float v = (d >= 0 && d < cT) ? x[((long)b * cT + d) * cF + x0 + tx]
                                     : nodes[((long)b * cN + n) * cF + x0 + tx];
        out_nn[((long)b * cN + n) * cF + x0 + tx] = v;
        __half h = __float2half(v);
        g_H[((long)b * cNC + n) * cF + x0 + tx] = h;
        t[ty + i * 8][tx] = h;
    }
    __syncthreads();
#pragma unroll
    for (int i = 0; i < 4; i++)
        g_HT[((long)b * cNC + x0 + ty + i * 8) * cF + y0 + tx] = t[tx][ty + i * 8];
}

// rest region passthrough (R14-proven)
__global__ void k_nodes_rest(const float4* __restrict__ x, const float4* __restrict__ nodes,
                             const int* __restrict__ T, float4* __restrict__ out_nn) {
    const long total = (long)cB * (cN - cNC) * 64;
    for (long idx = blockIdx.x * (long)blockDim.x + threadIdx.x; idx < total;
         idx += (long)gridDim.x * blockDim.x) {
        int b   = (int)(idx / ((cN - cNC) * 64));
        int rem = (int)(idx - (long)b * ((cN - cNC) * 64));
        int n = cNC + (rem >> 6), q = rem & 63;
        int d = n - T[b];
        long o = ((long)b * cN + n) * 64 + q;
        out_nn[o] = (d >= 0 && d < cT) ? x[((long)b * cT + d) * 64 + q] : nodes[o];
    }
}

// merged staging: z in [0,4) -> weight transpose W_z; z == 4 -> X-row cast
__global__ void k_stage(const float* __restrict__ W0, const float* __restrict__ W1,
                        const float* __restrict__ W2, const float* __restrict__ W3,
                        const float2* __restrict__ x) {
    int z = blockIdx.z;
    if (z < 4) {
        __shared__ float t[32][33];
        const float* Ws[4] = {W0, W1, W2, W3};
        int x0 = blockIdx.x * 32, y0 = blockIdx.y * 32;
        int tx = threadIdx.x, ty = threadIdx.y;
#pragma unroll
        for (int i = 0; i < 4; i++)
            t[ty + i * 8][tx] = Ws[z][(y0 + ty + i * 8) * cF + x0 + tx];
        __syncthreads();
#pragma unroll
        for (int i = 0; i < 4; i++)
            g_WT[z][(x0 + ty + i * 8) * cF + y0 + tx] = __float2half(t[tx][ty + i * 8]);
    } else {
        // X rows of g_H = cast(x): 262144 float2 over 64 blocks x 256 threads
        const long total = (long)MX * cF / 2;
        int tid = threadIdx.y * 32 + threadIdx.x;
        long base = ((long)blockIdx.y * 8 + blockIdx.x) * 256 + tid;   // 64 blocks
        for (long i = base; i < total; i += 64 * 256) {
            float2 v = x[i];
            *(__half2*)&g_H[(long)M1 * cF + i * 2] = __floats2half2_rn(v.x, v.y);
        }
    }
}

__global__ void k_zero4(float4* p, long n4) {
    for (long i = blockIdx.x * (long)blockDim.x + threadIdx.x; i < n4;
         i += (long)gridDim.x * blockDim.x)
        p[i] = make_float4(0.f, 0.f, 0.f, 0.f);
}

// Fused edge pass: out_ed/out_wt/out_tt passthrough + half adjacency atomics
__global__ void k_edges_fused(const int* __restrict__ edges, const float* __restrict__ w,
                              const int* __restrict__ T, const int* __restrict__ taus,
                              float* __restrict__ out_ed, float* __restrict__ out_wt,
                              float* __restrict__ out_tt) {
    if (blockIdx.x == 0 && threadIdx.x < cB)
        out_tt[threadIdx.x] = (float)(T[threadIdx.x] + taus[threadIdx.x]);
    const int total = cB * cE;
    for (int i = blockIdx.x * blockDim.x + threadIdx.x; i < total; i += gridDim.x * blockDim.x) {
        int b = i / cE, e = i - b * cE;
        int s = edges[(long)b * 2 * cE + e];
        int d = edges[(long)b * 2 * cE + cE + e];
        float wv = w[i];
        out_ed[(long)b * 2 * cE + e]      = (float)s;
        out_ed[(long)b * 2 * cE + cE + e] = (float)d;
        out_wt[i] = wv;
        if (s >= 0 && d >= 0 && s < cNC && d < cNC)
            atomicAdd(&g_adjh[((long)b * cNC + d) * cNC + s], __float2half(wv));
    }
}

// ---------------------------------------------------------------------------
// Launcher
// ---------------------------------------------------------------------------
extern "C" void kernel_launch(void* const* d_in, const int* in_sizes, int n_in,
                              void* d_out, int out_size) {
    const float* x       = (const float*)d_in[0];
    const int*   taus    = (const int*)  d_in[1];
    const float* nodes   = (const float*)d_in[2];
    const int*   edges   = (const int*)  d_in[3];
    const float* weights = (const float*)d_in[4];
    const int*   T       = (const int*)  d_in[5];
    const float* Ws1     = (const float*)d_in[6];
    const float* Wm1     = (const float*)d_in[7];
    const float* Ws2     = (const float*)d_in[8];
    const float* Wm2     = (const float*)d_in[9];

    float* out    = (float*)d_out;
    float* out_mx = out + OFF_MX;
    float* out_nn = out + OFF_NN;
    float* out_ed = out + OFF_ED;
    float* out_wt = out + OFF_WT;
    float* out_tt = out + OFF_TT;

    __half *p_adjh;
    cudaGetSymbolAddress((void**)&p_adjh, g_adjh);

    static cudaStream_t s1 = nullptr, s2 = nullptr, s3 = nullptr;
    static cudaEvent_t evF = nullptr, ev1 = nullptr, evX = nullptr, evW = nullptr;
    if (!s1) {
        cudaStreamCreateWithFlags(&s1, cudaStreamNonBlocking);
        cudaStreamCreateWithFlags(&s2, cudaStreamNonBlocking);
        cudaStreamCreateWithFlags(&s3, cudaStreamNonBlocking);
        cudaEventCreateWithFlags(&evF, cudaEventDisableTiming);
        cudaEventCreateWithFlags(&ev1, cudaEventDisableTiming);
        cudaEventCreateWithFlags(&evX, cudaEventDisableTiming);
        cudaEventCreateWithFlags(&evW, cudaEventDisableTiming);
        cudaFuncSetAttribute(k_layer1, cudaFuncAttributeMaxDynamicSharedMemorySize, FSMEM_BYTES);
        cudaFuncSetAttribute(k_layer2, cudaFuncAttributeMaxDynamicSharedMemorySize, L2SMEM_BYTES);
    }

    // fork
    cudaEventRecord(evF, 0);
    cudaStreamWaitEvent(s1, evF, 0);
    cudaStreamWaitEvent(s2, evF, 0);
    cudaStreamWaitEvent(s3, evF, 0);

    // s1: bulk passthrough (DRAM-bound, overlaps all compute)
    k_nodes_rest<<<4096, 256, 0, s1>>>((const float4*)x, (const float4*)nodes, T,
                                       (float4*)out_nn);
    cudaEventRecord(ev1, s1);

    // s2: compact nodes (out_nn + H + HT)
    k_nodes_compactT<<<dim3(8, 8, cB), dim3(32, 8), 0, s2>>>(nodes, x, T, out_nn);
    cudaEventRecord(evX, s2);

    // s3: merged staging — weight transposes + X-row cast, ONE launch
    k_stage<<<dim3(8, 8, 5), dim3(32, 8), 0, s3>>>(Ws1, Wm1, Ws2, Wm2, (const float2*)x);
    cudaEventRecord(evW, s3);

    // main: adjacency (half atomics) fused with edges/weights/tt passthrough
    k_zero4<<<1024, 256>>>((float4*)p_adjh, (long)cB * cNC * cNC / 8);
    k_edges_fused<<<2048, 256>>>(edges, weights, T, taus, out_ed, out_wt, out_tt);
    cudaStreamWaitEvent(0, evX, 0);
    cudaStreamWaitEvent(0, evW, 0);

    // fused layer 1: AH (smem) + h1 = tanh(H@Ws1 + AH@Wm1), one launch
    k_layer1<<<MEXT / 128, 512, FSMEM_BYTES>>>();

    // fused layer 2: aggpack + 16x256x512 GEMM + tanh -> out_mx, one launch
    k_layer2<<<cB, 256, L2SMEM_BYTES>>>(T, out_mx);

    // join passthrough branch
    cudaStreamWaitEvent(0, ev1, 0);
}

// round 17
// speedup vs baseline: 1.2696x; 1.2696x over previous
#include <cuda_runtime.h>
#include <cuda_fp16.h>
#include <math.h>
#include <stdint.h>

// Problem constants (fixed by the dataset)
constexpr int cB  = 128;
constexpr int cT  = 16;
constexpr int cF  = 256;
constexpr int cN  = 1024;
constexpr int cE  = 8192;
constexpr int cNC = 256;               // edge indices live in [0,256)
constexpr int M1   = cB * cNC;         // 32768 compact rows
constexpr int MX   = cB * cT;          // 2048 output rows
constexpr int MEXT = M1 + MX;          // 34816

// Output layout (flattened tuple, float32): mx | new_nodes | edges | weights | T+taus
constexpr long OFF_MX = 0;
constexpr long OFF_NN = (long)cB * cT * cF;
constexpr long OFF_ED = OFF_NN + (long)cB * cN * cF;
constexpr long OFF_WT = OFF_ED + (long)cB * 2 * cE;
constexpr long OFF_TT = OFF_WT + (long)cB * cE;

// stage tile sizes (halves), stride-40 layout
constexpr int FS_A = 128 * 40;                     // 5120
constexpr int FS_B = 256 * 40;                     // 10240
// k_layer1: A dbl + B dbl + 8 AH chunks (each 128x40)
constexpr int FSMEM_BYTES = (2 * FS_A + 2 * FS_B + 8 * FS_A) * 2;  // 143360 B
// k_layer2: adj fp32 [16][256] + F 16 chunks [16][40] + B dbl [256][40]
constexpr int L2_ADJ = cT * cNC * 4;               // 16384 B
constexpr int L2_F   = 16 * (cT * 40) * 2;         // 20480 B
constexpr int L2SMEM_BYTES = L2_ADJ + L2_F + 2 * FS_B * 2;  // 77824 B

// Scratch (__device__ globals — no allocation allowed)
__device__ __half g_adjh[(long)cB * cNC * cNC];   // half adjacency (atomic build)
__device__ __half g_H  [(long)MEXT * cF];         // [compact nodes | X rows], half
__device__ __half g_HT [(long)cB * cNC * cF];     // per-batch transposed H [feat][node]
__device__ __half g_h1 [(long)MEXT * cF];         // layer-1 hidden
__device__ __half g_WT [4][cF * cF];              // Ws1^T, Wm1^T, Ws2^T, Wm2^T (half)

// ---------------------------------------------------------------------------
// helpers
// ---------------------------------------------------------------------------
__device__ __forceinline__ void cpa16(void* s, const void* g) {
    unsigned sa = (unsigned)__cvta_generic_to_shared(s);
    asm volatile("cp.async.cg.shared.global [%0], [%1], 16;" :: "r"(sa), "l"(g));
}
__device__ __forceinline__ float fast_tanh(float x) {
    float ax = fabsf(x);
    float e;
    asm("ex2.approx.f32 %0, %1;" : "=f"(e) : "f"(ax * 2.8853900817779268f));
    float t = 1.0f - __fdividef(2.0f, e + 1.0f);
    return copysignf(t, x);
}
#define LDSM4(R, ADDR)                                                          \
    asm volatile("ldmatrix.sync.aligned.m8n8.x4.shared.b16 {%0,%1,%2,%3}, [%4];"\
                 : "=r"((R)[0]), "=r"((R)[1]), "=r"((R)[2]), "=r"((R)[3])       \
                 : "r"(ADDR))
#define MMA16(ACC, AF, B0, B1)                                                  \
    asm volatile("mma.sync.aligned.m16n8k16.row.col.f32.f16.f16.f32 "           \
                 "{%0,%1,%2,%3},{%4,%5,%6,%7},{%8,%9},{%0,%1,%2,%3};"           \
                 : "+f"((ACC)[0]), "+f"((ACC)[1]), "+f"((ACC)[2]), "+f"((ACC)[3])\
                 : "r"((AF)[0]), "r"((AF)[1]), "r"((AF)[2]), "r"((AF)[3]),      \
                   "r"(B0), "r"(B1))

// compute one 32-wide k-slab (2 ldmatrix slices) from smem bases aB/bB
#define COMPUTE_SLAB(aB, bB)                                                    \
    _Pragma("unroll")                                                           \
    for (int ks = 0; ks < 2; ks++) {                                            \
        unsigned af[4][4], bf[2][4];                                            \
        _Pragma("unroll")                                                       \
        for (int mi = 0; mi < 4; mi++) LDSM4(af[mi], (aB) + aoff[mi] + ks * 32);\
        _Pragma("unroll")                                                       \
        for (int pi = 0; pi < 2; pi++) LDSM4(bf[pi], (bB) + boff[pi] + ks * 32);\
        _Pragma("unroll")                                                       \
        for (int mi = 0; mi < 4; mi++)                                          \
            _Pragma("unroll")                                                   \
            for (int ni = 0; ni < 4; ni++)                                      \
                MMA16(acc[mi][ni], af[mi],                                      \
                      bf[ni >> 1][(ni & 1) * 2], bf[ni >> 1][(ni & 1) * 2 + 1]);\
    }

// ---------------------------------------------------------------------------
// k_layer1: fused (AH = Adj@H) + (h1 = tanh(H@Ws1 + AH@Wm1)), 272 CTAs.
// (R13-proven)
// ---------------------------------------------------------------------------
__global__ __launch_bounds__(512, 1) void k_layer1(void) {
    extern __shared__ __half sm[];
    __half* As[2] = { sm,            sm + FS_A };
    __half* Bs[2] = { sm + 2 * FS_A, sm + 2 * FS_A + FS_B };
    __half* AH    = sm + 2 * FS_A + 2 * FS_B;

    const int bx = blockIdx.x;
    const bool compact = bx < 2 * cB;
    const int tid = threadIdx.x, warp = tid >> 5, lane = tid & 31;
    const int g = lane >> 2, tg = lane & 3;
    const int wm = (warp & 1) * 64;
    const int wn = (warp >> 1) * 32;
    const int arow = tid >> 2, acol = (tid & 3) * 8;

    unsigned aBase[2] = { (unsigned)__cvta_generic_to_shared(As[0]),
                          (unsigned)__cvta_generic_to_shared(As[1]) };
    unsigned bBase[2] = { (unsigned)__cvta_generic_to_shared(Bs[0]),
                          (unsigned)__cvta_generic_to_shared(Bs[1]) };
    unsigned ahBase = (unsigned)__cvta_generic_to_shared(AH);

    int aoff[4], boff[2];
#pragma unroll
    for (int mi = 0; mi < 4; mi++)
        aoff[mi] = ((wm + mi * 16 + (lane & 15)) * 40 + (lane >> 4) * 8) * 2;
    {
        int q = lane >> 3, r = lane & 7;
#pragma unroll
        for (int pi = 0; pi < 2; pi++)
            boff[pi] = ((wn + pi * 16 + (q >> 1) * 8 + r) * 40 + (q & 1) * 8) * 2;
    }

    float acc[4][4][4];
#pragma unroll
    for (int a = 0; a < 4; a++)
#pragma unroll
        for (int b = 0; b < 4; b++)
#pragma unroll
            for (int c = 0; c < 4; c++) acc[a][b][c] = 0.f;

    const __half* Hrow = g_H + (long)bx * 128 * cF;

    if (compact) {
        const __half* adjA = g_adjh + (long)bx * 128 * cNC;
        const __half* HTb  = g_HT + (long)(bx >> 1) * cNC * cF;

#define LOAD1(KBI, BUF) do {                                                    \
    int kk_ = (KBI) * 32;                                                       \
    cpa16(&As[BUF][arow * 40 + acol], adjA + (long)arow * cNC + kk_ + acol);    \
    cpa16(&Bs[BUF][arow * 40 + acol], HTb + (long)arow * cF + kk_ + acol);      \
    cpa16(&Bs[BUF][(arow + 128) * 40 + acol],                                   \
          HTb + (long)(arow + 128) * cF + kk_ + acol);                          \
    asm volatile("cp.async.commit_group;");                                     \
} while (0)

        LOAD1(0, 0);
        for (int kb = 0; kb < 8; kb++) {
            asm volatile("cp.async.wait_group 0;" ::: "memory");
            __syncthreads();
            if (kb + 1 < 8) LOAD1(kb + 1, (kb + 1) & 1);
            COMPUTE_SLAB(aBase[kb & 1], bBase[kb & 1]);
        }
#undef LOAD1

#pragma unroll
        for (int mi = 0; mi < 4; mi++) {
            int r0 = wm + mi * 16 + g;
#pragma unroll
            for (int ni = 0; ni < 4; ni++) {
                int c0 = wn + ni * 8 + tg * 2;
                __half* chp = AH + (c0 >> 5) * FS_A + (c0 & 31);
                *(__half2*)&chp[r0 * 40] =
                    __floats2half2_rn(acc[mi][ni][0], acc[mi][ni][1]);
                *(__half2*)&chp[(r0 + 8) * 40] =
                    __floats2half2_rn(acc[mi][ni][2], acc[mi][ni][3]);
                acc[mi][ni][0] = acc[mi][ni][1] = acc[mi][ni][2] = acc[mi][ni][3] = 0.f;
            }
        }
        __syncthreads();
    }

    const int nkb2 = compact ? 16 : 8;

#define LOAD2(KBI, BUF) do {                                                    \
    int kk_ = ((KBI) & 7) * 32;                                                 \
    if ((KBI) < 8)                                                              \
        cpa16(&As[BUF][arow * 40 + acol], Hrow + (long)arow * cF + kk_ + acol); \
    const __half* Wt_ = ((KBI) < 8) ? g_WT[0] : g_WT[1];                        \
    cpa16(&Bs[BUF][arow * 40 + acol], Wt_ + (long)arow * cF + kk_ + acol);      \
    cpa16(&Bs[BUF][(arow + 128) * 40 + acol],                                   \
          Wt_ + (long)(arow + 128) * cF + kk_ + acol);                          \
    asm volatile("cp.async.commit_group;");                                     \
} while (0)

    LOAD2(0, 0);
    for (int kb = 0; kb < nkb2; kb++) {
        asm volatile("cp.async.wait_group 0;" ::: "memory");
        __syncthreads();
        if (kb + 1 < nkb2) LOAD2(kb + 1, (kb + 1) & 1);
        unsigned aB = (kb < 8) ? aBase[kb & 1]
                               : (ahBase + (unsigned)(kb - 8) * (FS_A * 2));
        COMPUTE_SLAB(aB, bBase[kb & 1]);
    }
#undef LOAD2

    __half* Dh = g_h1 + (long)bx * 128 * cF;
#pragma unroll
    for (int mi = 0; mi < 4; mi++) {
        int r0 = wm + mi * 16 + g;
#pragma unroll
        for (int ni = 0; ni < 4; ni++) {
            int c0 = wn + ni * 8 + tg * 2;
            *(__half2*)&Dh[(long)r0 * cF + c0] = __floats2half2_rn(
                fast_tanh(acc[mi][ni][0]), fast_tanh(acc[mi][ni][1]));
            *(__half2*)&Dh[(long)(r0 + 8) * cF + c0] = __floats2half2_rn(
                fast_tanh(acc[mi][ni][2]), fast_tanh(acc[mi][ni][3]));
        }
    }
}

// ---------------------------------------------------------------------------
// k_layer2: fused layer-2 per batch (128 CTAs, 256 threads). (R14-proven)
// ---------------------------------------------------------------------------
__global__ __launch_bounds__(256, 1) void k_layer2(const int* __restrict__ T,
                                                   float* __restrict__ out_mx) {
    extern __shared__ char smraw[];
    float*  adj_sm = (float*)smraw;                       // [16][256]
    __half* F_sm   = (__half*)(smraw + L2_ADJ);           // 16 chunks of [16][40]
    __half* Bs[2]  = { (__half*)(smraw + L2_ADJ + L2_F),
                       (__half*)(smraw + L2_ADJ + L2_F) + FS_B };

    const int b = blockIdx.x;
    const int tid = threadIdx.x, warp = tid >> 5, lane = tid & 31;
    const int g = lane >> 2, tg = lane & 3;
    const int Tb = T[b];

    unsigned fBase = (unsigned)__cvta_generic_to_shared(F_sm);
    unsigned bsBase[2] = { (unsigned)__cvta_generic_to_shared(Bs[0]),
                           (unsigned)__cvta_generic_to_shared(Bs[1]) };

#define LOADW(KBI, BUF) do {                                                    \
    const __half* Wt_ = ((KBI) < 8) ? g_WT[2] : g_WT[3];                        \
    int kk_ = ((KBI) & 7) * 32;                                                 \
    _Pragma("unroll")                                                           \
    for (int i = 0; i < 4; i++) {                                               \
        int u = tid * 4 + i;                                                    \
        int rw = u >> 2, cw = (u & 3) * 8;                                      \
        cpa16(&Bs[BUF][rw * 40 + cw], Wt_ + (long)rw * cF + kk_ + cw);          \
    }                                                                           \
    asm volatile("cp.async.commit_group;");                                     \
} while (0)

    LOADW(0, 0);

    // ---- phase A: aggpack ----
    {
        const int c = tid;
#pragma unroll
        for (int r = 0; r < cT; r++) {
            int row = Tb + r;
            adj_sm[r * cNC + c] = (row < cNC)
                ? __half2float(g_adjh[((long)b * cNC + row) * cNC + c]) : 0.f;
        }
        __syncthreads();

        float acc2[cT];
#pragma unroll
        for (int r = 0; r < cT; r++) acc2[r] = 0.f;

        const __half* h1b = g_h1 + (long)b * cNC * cF;
#pragma unroll 4
        for (int s = 0; s < cNC; s++) {
            float v = __half2float(h1b[(long)s * cF + c]);
#pragma unroll
            for (int r = 0; r < cT; r++) acc2[r] += adj_sm[r * cNC + s] * v;
        }

        const int ch = c >> 5, cc = c & 31;
#pragma unroll
        for (int r = 0; r < cT; r++) {
            int row = Tb + r;
            __half f1 = (row < cNC) ? g_h1[((long)b * cNC + row) * cF + c]
                                    : g_h1[((long)M1 + b * cT + r) * cF + c];
            F_sm[ch * (cT * 40) + r * 40 + cc] = f1;                          // K seg 0
            F_sm[(8 + ch) * (cT * 40) + r * 40 + cc] = __float2half(acc2[r]); // K seg 1
        }
    }
    __syncthreads();

    // ---- phase B: 16x256x512 GEMM ----
    const int wn = warp * 32;
    const int aoffA = ((lane & 15) * 40 + (lane >> 4) * 8) * 2;
    int boff[2];
    {
        int q = lane >> 3, r = lane & 7;
#pragma unroll
        for (int pi = 0; pi < 2; pi++)
            boff[pi] = ((wn + pi * 16 + (q >> 1) * 8 + r) * 40 + (q & 1) * 8) * 2;
    }

    float acc[4][4];
#pragma unroll
    for (int a = 0; a < 4; a++)
#pragma unroll
        for (int c = 0; c < 4; c++) acc[a][c] = 0.f;

    for (int kb = 0; kb < 16; kb++) {
        asm volatile("cp.async.wait_group 0;" ::: "memory");
        __syncthreads();
        if (kb + 1 < 16) LOADW(kb + 1, (kb + 1) & 1);
        const unsigned bB = bsBase[kb & 1];
        const unsigned aB = fBase + (unsigned)kb * (cT * 40 * 2);

#pragma unroll
        for (int ks = 0; ks < 2; ks++) {
            unsigned af[4], bf[2][4];
            LDSM4(af, aB + aoffA + ks * 32);
#pragma unroll
            for (int pi = 0; pi < 2; pi++) LDSM4(bf[pi], bB + boff[pi] + ks * 32);
#pragma unroll
            for (int ni = 0; ni < 4; ni++)
                MMA16(acc[ni], af,
                      bf[ni >> 1][(ni & 1) * 2], bf[ni >> 1][(ni & 1) * 2 + 1]);
        }
    }
#undef LOADW

    float* Db = out_mx + (long)b * cT * cF;
#pragma unroll
    for (int ni = 0; ni < 4; ni++) {
        int c0 = wn + ni * 8 + tg * 2;
        Db[(long)g * cF + c0]           = fast_tanh(acc[ni][0]);
        Db[(long)g * cF + c0 + 1]       = fast_tanh(acc[ni][1]);
        Db[(long)(g + 8) * cF + c0]     = fast_tanh(acc[ni][2]);
        Db[(long)(g + 8) * cF + c0 + 1] = fast_tanh(acc[ni][3]);
    }
}

// ---------------------------------------------------------------------------
// staging / passthrough kernels (R14-proven)
// ---------------------------------------------------------------------------
__global__ void k_nodes_compactT(const float* __restrict__ nodes, const float* __restrict__ x,
                                 const int* __restrict__ T, float* __restrict__ out_nn) {
    __shared__ __half t[32][33];
    int b = blockIdx.z;
    int x0 = blockIdx.x * 32, y0 = blockIdx.y * 32;
    int tx = threadIdx.x, ty = threadIdx.y;
    int Tb = T[b];
#pragma unroll
    for (int i = 0; i < 4; i++) {
        int n = y0 + ty + i * 8;
        int d = n - Tb;
        float v = (d >= 0 && d < cT) ? x[((long)b * cT + d) * cF + x0 + tx]
                                     : nodes[((long)b * cN + n) * cF + x0 + tx];
        out_nn[((long)b * cN + n) * cF + x0 + tx] = v;
        __half h = __float2half(v);
        g_H[((long)b * cNC + n) * cF + x0 + tx] = h;
        t[ty + i * 8][tx] = h;
    }
    __syncthreads();
#pragma unroll
    for (int i = 0; i < 4; i++)
        g_HT[((long)b * cNC + x0 + ty + i * 8) * cF + y0 + tx] = t[tx][ty + i * 8];
}

__global__ void k_nodes_rest(const float4* __restrict__ x, const float4* __restrict__ nodes,
                             const int* __restrict__ T, float4* __restrict__ out_nn) {
    const long total = (long)cB * (cN - cNC) * 64;
    for (long idx = blockIdx.x * (long)blockDim.x + threadIdx.x; idx < total;
         idx += (long)gridDim.x * blockDim.x) {
        int b   = (int)(idx / ((cN - cNC) * 64));
        int rem = (int)(idx - (long)b * ((cN - cNC) * 64));
        int n = cNC + (rem >> 6), q = rem & 63;
        int d = n - T[b];
        long o = ((long)b * cN + n) * 64 + q;
        out_nn[o] = (d >= 0 && d < cT) ? x[((long)b * cT + d) * 64 + q] : nodes[o];
    }
}

__global__ void k_castx(const float2* __restrict__ x) {
    const long total = (long)MX * cF / 2;
    for (long i = blockIdx.x * (long)blockDim.x + threadIdx.x; i < total;
         i += (long)gridDim.x * blockDim.x) {
        float2 v = x[i];
        *(__half2*)&g_H[(long)M1 * cF + i * 2] = __floats2half2_rn(v.x, v.y);
    }
}

__global__ void k_zero4(float4* p, long n4) {
    for (long i = blockIdx.x * (long)blockDim.x + threadIdx.x; i < n4;
         i += (long)gridDim.x * blockDim.x)
        p[i] = make_float4(0.f, 0.f, 0.f, 0.f);
}

// Fused edge pass: out_ed/out_wt/out_tt passthrough + half adjacency atomics
__global__ void k_edges_fused(const int* __restrict__ edges, const float* __restrict__ w,
                              const int* __restrict__ T, const int* __restrict__ taus,
                              float* __restrict__ out_ed, float* __restrict__ out_wt,
                              float* __restrict__ out_tt) {
    if (blockIdx.x == 0 && threadIdx.x < cB)
        out_tt[threadIdx.x] = (float)(T[threadIdx.x] + taus[threadIdx.x]);
    const int total = cB * cE;
    for (int i = blockIdx.x * blockDim.x + threadIdx.x; i < total; i += gridDim.x * blockDim.x) {
        int b = i / cE, e = i - b * cE;
        int s = edges[(long)b * 2 * cE + e];
        int d = edges[(long)b * 2 * cE + cE + e];
        float wv = w[i];
        out_ed[(long)b * 2 * cE + e]      = (float)s;
        out_ed[(long)b * 2 * cE + cE + e] = (float)d;
        out_wt[i] = wv;
        if (s >= 0 && d >= 0 && s < cNC && d < cNC)
            atomicAdd(&g_adjh[((long)b * cNC + d) * cNC + s], __float2half(wv));
    }
}

__global__ void k_packWT(const float* __restrict__ W0, const float* __restrict__ W1,
                         const float* __restrict__ W2, const float* __restrict__ W3) {
    __shared__ float t[32][33];
    const float* Ws[4] = {W0, W1, W2, W3};
    int z = blockIdx.z;
    int x0 = blockIdx.x * 32, y0 = blockIdx.y * 32;
    int tx = threadIdx.x, ty = threadIdx.y;
#pragma unroll
    for (int i = 0; i < 4; i++)
        t[ty + i * 8][tx] = Ws[z][(y0 + ty + i * 8) * cF + x0 + tx];
    __syncthreads();
#pragma unroll
    for (int i = 0; i < 4; i++)
        g_WT[z][(x0 + ty + i * 8) * cF + y0 + tx] = __float2half(t[tx][ty + i * 8]);
}

// ---------------------------------------------------------------------------
// Launcher (R14-proven topology)
// ---------------------------------------------------------------------------
extern "C" void kernel_launch(void* const* d_in, const int* in_sizes, int n_in,
                              void* d_out, int out_size) {
    const float* x       = (const float*)d_in[0];
    const int*   taus    = (const int*)  d_in[1];
    const float* nodes   = (const float*)d_in[2];
    const int*   edges   = (const int*)  d_in[3];
    const float* weights = (const float*)d_in[4];
    const int*   T       = (const int*)  d_in[5];
    const float* Ws1     = (const float*)d_in[6];
    const float* Wm1     = (const float*)d_in[7];
    const float* Ws2     = (const float*)d_in[8];
    const float* Wm2     = (const float*)d_in[9];

    float* out    = (float*)d_out;
    float* out_mx = out + OFF_MX;
    float* out_nn = out + OFF_NN;
    float* out_ed = out + OFF_ED;
    float* out_wt = out + OFF_WT;
    float* out_tt = out + OFF_TT;

    __half *p_adjh;
    cudaGetSymbolAddress((void**)&p_adjh, g_adjh);

    static cudaStream_t s1 = nullptr, s2 = nullptr, s3 = nullptr;
    static cudaEvent_t evF = nullptr, ev1 = nullptr, evX = nullptr, evW = nullptr;
    if (!s1) {
        cudaStreamCreateWithFlags(&s1, cudaStreamNonBlocking);
        cudaStreamCreateWithFlags(&s2, cudaStreamNonBlocking);
        cudaStreamCreateWithFlags(&s3, cudaStreamNonBlocking);
        cudaEventCreateWithFlags(&evF, cudaEventDisableTiming);
        cudaEventCreateWithFlags(&ev1, cudaEventDisableTiming);
        cudaEventCreateWithFlags(&evX, cudaEventDisableTiming);
        cudaEventCreateWithFlags(&evW, cudaEventDisableTiming);
        cudaFuncSetAttribute(k_layer1, cudaFuncAttributeMaxDynamicSharedMemorySize, FSMEM_BYTES);
        cudaFuncSetAttribute(k_layer2, cudaFuncAttributeMaxDynamicSharedMemorySize, L2SMEM_BYTES);
    }

    // fork
    cudaEventRecord(evF, 0);
    cudaStreamWaitEvent(s1, evF, 0);
    cudaStreamWaitEvent(s2, evF, 0);
    cudaStreamWaitEvent(s3, evF, 0);

    // s1: bulk passthrough (DRAM-bound, overlaps all compute)
    k_nodes_rest<<<4096, 256, 0, s1>>>((const float4*)x, (const float4*)nodes, T,
                                       (float4*)out_nn);
    cudaEventRecord(ev1, s1);

    // s2: compact nodes (out_nn + H + HT)
    k_nodes_compactT<<<dim3(8, 8, cB), dim3(32, 8), 0, s2>>>(nodes, x, T, out_nn);
    cudaEventRecord(evX, s2);

    // s3: X rows of H + packed weights (independent of s2)
    k_castx<<<512, 256, 0, s3>>>((const float2*)x);
    k_packWT<<<dim3(8, 8, 4), dim3(32, 8), 0, s3>>>(Ws1, Wm1, Ws2, Wm2);
    cudaEventRecord(evW, s3);

    // main: adjacency (half atomics) fused with edges/weights/tt passthrough
    k_zero4<<<1024, 256>>>((float4*)p_adjh, (long)cB * cNC * cNC / 8);
    k_edges_fused<<<2048, 256>>>(edges, weights, T, taus, out_ed, out_wt, out_tt);
    cudaStreamWaitEvent(0, evX, 0);
    cudaStreamWaitEvent(0, evW, 0);

    // fused layer 1: AH (smem) + h1 = tanh(H@Ws1 + AH@Wm1), one launch
    k_layer1<<<MEXT / 128, 512, FSMEM_BYTES>>>();

    // fused layer 2: aggpack + 16x256x512 GEMM + tanh -> out_mx, one launch
    k_layer2<<<cB, 256, L2SMEM_BYTES>>>(T, out_mx);

    // join passthrough branch
    cudaStreamWaitEvent(0, ev1, 0);
}